// round 5
// baseline (speedup 1.0000x reference)
#include <cuda_runtime.h>
#include <math.h>

// ---------------- static scratch (no allocations allowed) ----------------
#define MAXN 50176
#define MAXE 560128   // E + N upper bound

__device__ __align__(16) float g_xl[MAXN * 128];
__device__ __align__(16) float g_xr[MAXN * 128];
__device__ int g_count[MAXN];
__device__ int g_rowstart[MAXN + 1];
__device__ int g_pos[MAXN];
__device__ int g_srcs[MAXE];
__device__ float g_pool[128];
__device__ unsigned g_ticket;

__device__ __forceinline__ unsigned f2tf32(float f) {
    unsigned u;
    asm("cvt.rna.tf32.f32 %0, %1;" : "=r"(u) : "f"(f));
    return u;
}

__device__ __forceinline__ void mma_tf32(float* c, const unsigned* a, unsigned b0, unsigned b1) {
    asm volatile(
        "mma.sync.aligned.m16n8k8.row.col.f32.tf32.tf32.f32 "
        "{%0,%1,%2,%3}, {%4,%5,%6,%7}, {%8,%9}, {%0,%1,%2,%3};\n"
        : "+f"(c[0]), "+f"(c[1]), "+f"(c[2]), "+f"(c[3])
        : "r"(a[0]), "r"(a[1]), "r"(a[2]), "r"(a[3]), "r"(b0), "r"(b1));
}

// ---------------- GEMM (tf32 tensor cores): out = x@W + b ----------------
__global__ __launch_bounds__(256) void gemm_kernel(
    const float* __restrict__ x,
    const float* __restrict__ Wl, const float* __restrict__ bl,
    const float* __restrict__ Wr, const float* __restrict__ br,
    int n)
{
    __shared__ unsigned xs[128][36];
    __shared__ unsigned ws[32][132];

    int row0 = blockIdx.x * 128;
    int t    = blockIdx.y;
    const float* W = t ? Wr : Wl;
    const float* b = t ? br : bl;
    float* outp    = t ? g_xr : g_xl;

    int tid  = threadIdx.x;
    int lane = tid & 31;
    int wid  = tid >> 5;
    int wm   = wid & 3;
    int wn   = wid >> 2;

    // folded init: CSR counts start at 1 (self loop), pool/ticket reset
    if (t == 0) {
        if (tid < 128 && row0 + tid < n) g_count[row0 + tid] = 1;
        if (blockIdx.x == 0) {
            if (tid < 128) g_pool[tid] = 0.0f;
            if (tid == 0)  g_ticket = 0u;
        }
    }

    float c[16][4];
#pragma unroll
    for (int i = 0; i < 16; i++)
#pragma unroll
        for (int j = 0; j < 4; j++) c[i][j] = 0.0f;

    int q = lane & 3, r = lane >> 2;

    for (int k0 = 0; k0 < 128; k0 += 32) {
#pragma unroll
        for (int i = 0; i < 4; i++) {
            int idx = tid + i * 256;
            int rr = idx >> 3, c4 = idx & 7;
            float4 v = make_float4(0.f, 0.f, 0.f, 0.f);
            int gr = row0 + rr;
            if (gr < n) v = *(const float4*)(x + (size_t)gr * 128 + k0 + c4 * 4);
            unsigned* row = xs[rr];
            int g = c4 >> 1, j = c4 & 1;
            row[g * 8 + 0 + j] = f2tf32(v.x);
            row[g * 8 + 2 + j] = f2tf32(v.y);
            row[g * 8 + 4 + j] = f2tf32(v.z);
            row[g * 8 + 6 + j] = f2tf32(v.w);
        }
#pragma unroll
        for (int i = 0; i < 4; i++) {
            int idx = tid + i * 256;
            int k = idx >> 5, c4 = idx & 31;
            float4 v = *(const float4*)(W + (size_t)(k0 + k) * 128 + c4 * 4);
            unsigned* row = ws[k];
            int n0  = c4 * 4;
            int s   = n0 >> 6;
            int ln  = n0 & 63;
            unsigned base = s * 64 + (ln >> 3);
            int qb = ln & 7;
            row[base + (qb + 0) * 8] = f2tf32(v.x);
            row[base + (qb + 1) * 8] = f2tf32(v.y);
            row[base + (qb + 2) * 8] = f2tf32(v.z);
            row[base + (qb + 3) * 8] = f2tf32(v.w);
        }
        __syncthreads();

#pragma unroll
        for (int g = 0; g < 4; g++) {
            unsigned a[2][4];
#pragma unroll
            for (int mt = 0; mt < 2; mt++) {
                int rowA = wm * 32 + mt * 16 + r;
                uint2 lo = *(uint2*)&xs[rowA][g * 8 + 2 * q];
                uint2 hi = *(uint2*)&xs[rowA + 8][g * 8 + 2 * q];
                a[mt][0] = lo.x; a[mt][2] = lo.y;
                a[mt][1] = hi.x; a[mt][3] = hi.y;
            }
            int kb = g * 8 + q;
            uint4 b0a = *(uint4*)&ws[kb][wn * 64 + r * 8];
            uint4 b0b = *(uint4*)&ws[kb][wn * 64 + r * 8 + 4];
            uint4 b1a = *(uint4*)&ws[kb + 4][wn * 64 + r * 8];
            uint4 b1b = *(uint4*)&ws[kb + 4][wn * 64 + r * 8 + 4];
            unsigned b0r[8] = {b0a.x, b0a.y, b0a.z, b0a.w, b0b.x, b0b.y, b0b.z, b0b.w};
            unsigned b1r[8] = {b1a.x, b1a.y, b1a.z, b1a.w, b1b.x, b1b.y, b1b.z, b1b.w};
#pragma unroll
            for (int mt = 0; mt < 2; mt++)
#pragma unroll
                for (int nt = 0; nt < 8; nt++)
                    mma_tf32(c[mt * 8 + nt], a[mt], b0r[nt], b1r[nt]);
        }
        __syncthreads();
    }

#pragma unroll
    for (int mt = 0; mt < 2; mt++) {
#pragma unroll
        for (int nt = 0; nt < 8; nt++) {
            int col = wn * 64 + nt * 8 + 2 * q;
            float2 bb = *(const float2*)(b + col);
            int grow = row0 + wm * 32 + mt * 16 + r;
            float* cc = c[mt * 8 + nt];
            if (grow < n) {
                float2 o = make_float2(cc[0] + bb.x, cc[1] + bb.y);
                *(float2*)(outp + (size_t)grow * 128 + col) = o;
            }
            if (grow + 8 < n) {
                float2 o = make_float2(cc[2] + bb.x, cc[3] + bb.y);
                *(float2*)(outp + (size_t)(grow + 8) * 128 + col) = o;
            }
        }
    }
}

// ---------------- CSR build ----------------
__global__ __launch_bounds__(512) void hist_kernel(const int* __restrict__ ei, int E) {
    int e = blockIdx.x * blockDim.x + threadIdx.x;
    if (e < E) atomicAdd(&g_count[__ldg(ei + E + e)], 1);
}

__global__ __launch_bounds__(1024) void scan_kernel(int n) {
    __shared__ int partials[1024];
    int t = threadIdx.x;
    int ch = (n + 1023) >> 10;
    int lo = t * ch, hi = min(lo + ch, n);
    int s = 0;
    for (int i = lo; i < hi; i++) s += g_count[i];
    partials[t] = s;
    __syncthreads();
    for (int off = 1; off < 1024; off <<= 1) {
        int v = (t >= off) ? partials[t - off] : 0;
        __syncthreads();
        partials[t] += v;
        __syncthreads();
    }
    int run = partials[t] - s;   // exclusive prefix
    for (int i = lo; i < hi; i++) {
        g_rowstart[i] = run;
        g_srcs[run]   = i;       // self-loop pre-seeded at first slot
        g_pos[i]      = run + 1;
        run += g_count[i];
    }
    if (t == 1023) g_rowstart[n] = partials[1023];
}

__global__ __launch_bounds__(512) void scatter_kernel(const int* __restrict__ ei, int E) {
    int e = blockIdx.x * blockDim.x + threadIdx.x;
    if (e >= E) return;
    int dst = __ldg(ei + E + e);
    int slot = atomicAdd(&g_pos[dst], 1);
    g_srcs[slot] = __ldg(ei + e);
}

// ---------------- fused CSR attention + normalize + BN + pool + head ----------------
__device__ __forceinline__ float lrelu(float v) { return v > 0.f ? v : 0.2f * v; }

__global__ __launch_bounds__(256) void attn_kernel(
    const float* __restrict__ att,   const float* __restrict__ bias1,
    const float* __restrict__ gamma, const float* __restrict__ beta,
    const float* __restrict__ mean,  const float* __restrict__ var,
    const float* __restrict__ Wc,    const float* __restrict__ bc,
    float* __restrict__ out, int n)
{
    int lane = threadIdx.x & 31;
    int wib  = threadIdx.x >> 5;
    int warp = blockIdx.x * 8 + wib;
    int nwarps = gridDim.x * 8;

    float4 av = *(const float4*)(att + lane * 4);
    float4 gm = *(const float4*)(gamma + lane * 4);
    float4 bt = *(const float4*)(beta  + lane * 4);
    float4 mn = *(const float4*)(mean  + lane * 4);
    float4 vr = *(const float4*)(var   + lane * 4);
    float4 b1 = *(const float4*)(bias1 + lane * 4);
    float4 sc = make_float4(gm.x * rsqrtf(vr.x + 1e-5f), gm.y * rsqrtf(vr.y + 1e-5f),
                            gm.z * rsqrtf(vr.z + 1e-5f), gm.w * rsqrtf(vr.w + 1e-5f));
    float4 sh = make_float4(bt.x - mn.x * sc.x, bt.y - mn.y * sc.y,
                            bt.z - mn.z * sc.z, bt.w - mn.w * sc.w);

    float4 pool = make_float4(0.f, 0.f, 0.f, 0.f);

    for (int i = warp; i < n; i += nwarps) {
        float4 xrv = *(const float4*)(g_xr + (size_t)i * 128 + lane * 4);
        int rs = g_rowstart[i], re = g_rowstart[i + 1];
        float4 acc = make_float4(0.f, 0.f, 0.f, 0.f);
        float denom = 0.0f;

        for (int s0 = rs; s0 < re; s0 += 4) {
            int cnt = re - s0; if (cnt > 4) cnt = 4;
            int src[4];
#pragma unroll
            for (int k = 0; k < 4; k++)
                src[k] = (k < cnt) ? __ldg(g_srcs + s0 + k) : i;
            float4 xlv[4];
#pragma unroll
            for (int k = 0; k < 4; k++)
                xlv[k] = *(const float4*)(g_xl + (size_t)src[k] * 128 + lane * 4);

            float v[4];
#pragma unroll
            for (int k = 0; k < 4; k++) {
                v[k] = av.x * lrelu(xlv[k].x + xrv.x)
                     + av.y * lrelu(xlv[k].y + xrv.y)
                     + av.z * lrelu(xlv[k].z + xrv.z)
                     + av.w * lrelu(xlv[k].w + xrv.w);
            }
#pragma unroll
            for (int o = 16; o; o >>= 1) {
#pragma unroll
                for (int k = 0; k < 4; k++)
                    v[k] += __shfl_xor_sync(0xffffffffu, v[k], o);
            }
#pragma unroll
            for (int k = 0; k < 4; k++) {
                if (k < cnt) {
                    float w = __expf(v[k]);
                    denom += w;
                    acc.x += w * xlv[k].x; acc.y += w * xlv[k].y;
                    acc.z += w * xlv[k].z; acc.w += w * xlv[k].w;
                }
            }
        }

        float inv = 1.0f / denom;
        float4 h;
        h.x = (acc.x * inv + b1.x) * sc.x + sh.x;
        h.y = (acc.y * inv + b1.y) * sc.y + sh.y;
        h.z = (acc.z * inv + b1.z) * sc.z + sh.z;
        h.w = (acc.w * inv + b1.w) * sc.w + sh.w;
        pool.x += h.x; pool.y += h.y; pool.z += h.z; pool.w += h.w;
    }

    // block-level reduction of pool, then one atomicAdd per dim per block
    __shared__ float4 sp[8][32];
    sp[wib][lane] = pool;
    __syncthreads();
    if (wib == 0) {
        float4 tot = sp[0][lane];
#pragma unroll
        for (int w = 1; w < 8; w++) {
            float4 p = sp[w][lane];
            tot.x += p.x; tot.y += p.y; tot.z += p.z; tot.w += p.w;
        }
        atomicAdd(&g_pool[lane * 4 + 0], tot.x);
        atomicAdd(&g_pool[lane * 4 + 1], tot.y);
        atomicAdd(&g_pool[lane * 4 + 2], tot.z);
        atomicAdd(&g_pool[lane * 4 + 3], tot.w);
    }
    __threadfence();

    __shared__ unsigned ticket;
    if (threadIdx.x == 0) ticket = atomicAdd(&g_ticket, 1u);
    __syncthreads();
    if (ticket != gridDim.x - 1) return;

    // last block: head = mean pool -> linear(5) -> softmax
    __shared__ float gsh[128];
    __shared__ float lg[5];
    int t = threadIdx.x;
    if (t < 128) gsh[t] = __ldcg(&g_pool[t]) / (float)n;
    __syncthreads();
    if (t < 5) {
        float s = bc[t];
#pragma unroll
        for (int k = 0; k < 128; k++) s += gsh[k] * Wc[k * 5 + t];
        lg[t] = s;
    }
    __syncthreads();
    if (t == 0) {
        float m = lg[0];
        for (int i = 1; i < 5; i++) m = fmaxf(m, lg[i]);
        float e[5], den = 0.f;
        for (int i = 0; i < 5; i++) { e[i] = expf(lg[i] - m); den += e[i]; }
        for (int i = 0; i < 5; i++) out[i] = e[i] / den;
    }
}

// ---------------- launcher ----------------
extern "C" void kernel_launch(void* const* d_in, const int* in_sizes, int n_in,
                              void* d_out, int out_size)
{
    const float* x     = (const float*)d_in[0];
    const int*   ei    = (const int*)d_in[1];
    const float* Wl    = (const float*)d_in[2];
    const float* bl    = (const float*)d_in[3];
    const float* Wr    = (const float*)d_in[4];
    const float* br    = (const float*)d_in[5];
    const float* att   = (const float*)d_in[6];
    const float* bias1 = (const float*)d_in[7];
    const float* gam   = (const float*)d_in[8];
    const float* bet   = (const float*)d_in[9];
    const float* mea   = (const float*)d_in[10];
    const float* var   = (const float*)d_in[11];
    const float* Wc    = (const float*)d_in[12];
    const float* bc    = (const float*)d_in[13];
    float* out = (float*)d_out;

    int n  = in_sizes[0] / 128;
    int E  = in_sizes[1] / 2;

    dim3 gg((n + 127) / 128, 2);
    gemm_kernel<<<gg, 256>>>(x, Wl, bl, Wr, br, n);   // also inits count/pool/ticket

    hist_kernel<<<(E + 511) / 512, 512>>>(ei, E);
    scan_kernel<<<1, 1024>>>(n);
    scatter_kernel<<<(E + 511) / 512, 512>>>(ei, E);

    attn_kernel<<<1184, 256>>>(att, bias1, gam, bet, mea, var, Wc, bc, out, n);
}

// round 6
// speedup vs baseline: 1.7576x; 1.7576x over previous
#include <cuda_runtime.h>
#include <cuda_bf16.h>
#include <math.h>

// ---------------- static scratch (no allocations allowed) ----------------
#define MAXN 50176

__device__ __align__(16) __nv_bfloat16 g_xl[MAXN * 128];
__device__ __align__(16) __nv_bfloat16 g_xr[MAXN * 128];
__device__ __align__(16) float g_acc[MAXN * 128];
__device__ float g_denom[MAXN];
__device__ float g_pool[128];
__device__ unsigned g_ticket;

__device__ __forceinline__ unsigned f2tf32(float f) {
    unsigned u;
    asm("cvt.rna.tf32.f32 %0, %1;" : "=r"(u) : "f"(f));
    return u;
}

__device__ __forceinline__ void mma_tf32(float* c, const unsigned* a, unsigned b0, unsigned b1) {
    asm volatile(
        "mma.sync.aligned.m16n8k8.row.col.f32.tf32.tf32.f32 "
        "{%0,%1,%2,%3}, {%4,%5,%6,%7}, {%8,%9}, {%0,%1,%2,%3};\n"
        : "+f"(c[0]), "+f"(c[1]), "+f"(c[2]), "+f"(c[3])
        : "r"(a[0]), "r"(a[1]), "r"(a[2]), "r"(a[3]), "r"(b0), "r"(b1));
}

// ---------------- GEMM (tf32 tensor cores): out = bf16(x@W + b) ----------------
// grid = (ceil(n/128), 2): y=0 -> (Wl,bl)->g_xl, y=1 -> (Wr,br)->g_xr.
// 256 thr = 8 warps (4M x 2N), warp does 32x64 via 2x8 m16n8k8 tiles, K by 32.
// blockIdx.y==0 blocks also zero g_acc/g_denom/g_pool/g_ticket (init folded in).
__global__ __launch_bounds__(256) void gemm_kernel(
    const float* __restrict__ x,
    const float* __restrict__ Wl, const float* __restrict__ bl,
    const float* __restrict__ Wr, const float* __restrict__ br,
    int n)
{
    __shared__ unsigned xs[128][36];
    __shared__ unsigned ws[32][132];

    int row0 = blockIdx.x * 128;
    int t    = blockIdx.y;
    const float* W = t ? Wr : Wl;
    const float* b = t ? br : bl;
    __nv_bfloat16* outp = t ? g_xr : g_xl;

    int tid  = threadIdx.x;
    int lane = tid & 31;
    int wid  = tid >> 5;
    int wm   = wid & 3;
    int wn   = wid >> 2;

    // folded init
    if (t == 0) {
        float4 z = make_float4(0.f, 0.f, 0.f, 0.f);
        float4* accp = (float4*)(g_acc + (size_t)row0 * 128);
#pragma unroll
        for (int i = 0; i < 16; i++) accp[tid + i * 256] = z;
        if (tid < 128) g_denom[row0 + tid] = 0.0f;
        if (blockIdx.x == 0) {
            if (tid < 128) g_pool[tid] = 0.0f;
            if (tid == 0)  g_ticket = 0u;
        }
    }

    float c[16][4];
#pragma unroll
    for (int i = 0; i < 16; i++)
#pragma unroll
        for (int j = 0; j < 4; j++) c[i][j] = 0.0f;

    int q = lane & 3, r = lane >> 2;

    for (int k0 = 0; k0 < 128; k0 += 32) {
#pragma unroll
        for (int i = 0; i < 4; i++) {
            int idx = tid + i * 256;
            int rr = idx >> 3, c4 = idx & 7;
            float4 v = make_float4(0.f, 0.f, 0.f, 0.f);
            int gr = row0 + rr;
            if (gr < n) v = *(const float4*)(x + (size_t)gr * 128 + k0 + c4 * 4);
            unsigned* row = xs[rr];
            int g = c4 >> 1, j = c4 & 1;
            row[g * 8 + 0 + j] = f2tf32(v.x);
            row[g * 8 + 2 + j] = f2tf32(v.y);
            row[g * 8 + 4 + j] = f2tf32(v.z);
            row[g * 8 + 6 + j] = f2tf32(v.w);
        }
#pragma unroll
        for (int i = 0; i < 4; i++) {
            int idx = tid + i * 256;
            int k = idx >> 5, c4 = idx & 31;
            float4 v = *(const float4*)(W + (size_t)(k0 + k) * 128 + c4 * 4);
            unsigned* row = ws[k];
            int n0  = c4 * 4;
            int s   = n0 >> 6;
            int ln  = n0 & 63;
            unsigned base = s * 64 + (ln >> 3);
            int qb = ln & 7;
            row[base + (qb + 0) * 8] = f2tf32(v.x);
            row[base + (qb + 1) * 8] = f2tf32(v.y);
            row[base + (qb + 2) * 8] = f2tf32(v.z);
            row[base + (qb + 3) * 8] = f2tf32(v.w);
        }
        __syncthreads();

#pragma unroll
        for (int g = 0; g < 4; g++) {
            unsigned a[2][4];
#pragma unroll
            for (int mt = 0; mt < 2; mt++) {
                int rowA = wm * 32 + mt * 16 + r;
                uint2 lo = *(uint2*)&xs[rowA][g * 8 + 2 * q];
                uint2 hi = *(uint2*)&xs[rowA + 8][g * 8 + 2 * q];
                a[mt][0] = lo.x; a[mt][2] = lo.y;
                a[mt][1] = hi.x; a[mt][3] = hi.y;
            }
            int kb = g * 8 + q;
            uint4 b0a = *(uint4*)&ws[kb][wn * 64 + r * 8];
            uint4 b0b = *(uint4*)&ws[kb][wn * 64 + r * 8 + 4];
            uint4 b1a = *(uint4*)&ws[kb + 4][wn * 64 + r * 8];
            uint4 b1b = *(uint4*)&ws[kb + 4][wn * 64 + r * 8 + 4];
            unsigned b0r[8] = {b0a.x, b0a.y, b0a.z, b0a.w, b0b.x, b0b.y, b0b.z, b0b.w};
            unsigned b1r[8] = {b1a.x, b1a.y, b1a.z, b1a.w, b1b.x, b1b.y, b1b.z, b1b.w};
#pragma unroll
            for (int mt = 0; mt < 2; mt++)
#pragma unroll
                for (int nt = 0; nt < 8; nt++)
                    mma_tf32(c[mt * 8 + nt], a[mt], b0r[nt], b1r[nt]);
        }
        __syncthreads();
    }

    // epilogue: +bias -> bf16x2 stores
#pragma unroll
    for (int mt = 0; mt < 2; mt++) {
#pragma unroll
        for (int nt = 0; nt < 8; nt++) {
            int col = wn * 64 + nt * 8 + 2 * q;
            float2 bb = *(const float2*)(b + col);
            int grow = row0 + wm * 32 + mt * 16 + r;
            float* cc = c[mt * 8 + nt];
            if (grow < n) {
                __nv_bfloat162 o = __float22bfloat162_rn(
                    make_float2(cc[0] + bb.x, cc[1] + bb.y));
                *(__nv_bfloat162*)(outp + (size_t)grow * 128 + col) = o;
            }
            if (grow + 8 < n) {
                __nv_bfloat162 o = __float22bfloat162_rn(
                    make_float2(cc[2] + bb.x, cc[3] + bb.y));
                *(__nv_bfloat162*)(outp + (size_t)(grow + 8) * 128 + col) = o;
            }
        }
    }
}

// ---------------- fused edge pass (bf16 gathers, fp32 RED) ----------------
__device__ __forceinline__ float lrelu(float v) { return v > 0.f ? v : 0.2f * v; }

__device__ __forceinline__ float4 ld_bf16x4(const __nv_bfloat16* p) {
    uint2 u = *(const uint2*)p;
    float2 f0 = __bfloat1622float2(*(__nv_bfloat162*)&u.x);
    float2 f1 = __bfloat1622float2(*(__nv_bfloat162*)&u.y);
    return make_float4(f0.x, f0.y, f1.x, f1.y);
}

__global__ __launch_bounds__(256) void edge_fused_kernel(
    const int* __restrict__ ei, const float* __restrict__ att, int E, int TE)
{
    int w    = (blockIdx.x * blockDim.x + threadIdx.x) >> 5;
    int lane = threadIdx.x & 31;
    int base = w * 4;
    if (base >= TE) return;

    float4 av = *(const float4*)(att + lane * 4);

    int s[4], d[4];
    bool ok[4];
#pragma unroll
    for (int k = 0; k < 4; k++) {
        int e = base + k;
        ok[k] = (e < TE);
        if (!ok[k]) { s[k] = 0; d[k] = 0; }
        else if (e < E) { s[k] = __ldg(ei + e); d[k] = __ldg(ei + E + e); }
        else { s[k] = d[k] = e - E; }
    }

    float4 xlv[4], xrv[4];
#pragma unroll
    for (int k = 0; k < 4; k++) {
        xlv[k] = ld_bf16x4(g_xl + (size_t)s[k] * 128 + lane * 4);
        xrv[k] = ld_bf16x4(g_xr + (size_t)d[k] * 128 + lane * 4);
    }

    float v[4];
#pragma unroll
    for (int k = 0; k < 4; k++) {
        v[k] = av.x * lrelu(xlv[k].x + xrv[k].x)
             + av.y * lrelu(xlv[k].y + xrv[k].y)
             + av.z * lrelu(xlv[k].z + xrv[k].z)
             + av.w * lrelu(xlv[k].w + xrv[k].w);
    }
#pragma unroll
    for (int o = 16; o; o >>= 1) {
#pragma unroll
        for (int k = 0; k < 4; k++)
            v[k] += __shfl_xor_sync(0xffffffffu, v[k], o);
    }

#pragma unroll
    for (int k = 0; k < 4; k++) {
        if (!ok[k]) continue;
        float wgt = __expf(v[k]);
        if (lane == 0) {
            asm volatile("red.global.add.f32 [%0], %1;"
                         :: "l"(g_denom + d[k]), "f"(wgt) : "memory");
        }
        float* dstp = g_acc + (size_t)d[k] * 128 + lane * 4;
        asm volatile("red.global.add.v4.f32 [%0], {%1, %2, %3, %4};"
                     :: "l"(dstp), "f"(wgt * xlv[k].x), "f"(wgt * xlv[k].y),
                        "f"(wgt * xlv[k].z), "f"(wgt * xlv[k].w)
                     : "memory");
    }
}

// ---------------- node pass + fused head ----------------
__global__ __launch_bounds__(128) void node_kernel(
    const float* __restrict__ bias1,
    const float* __restrict__ gamma, const float* __restrict__ beta,
    const float* __restrict__ mean,  const float* __restrict__ var,
    const float* __restrict__ Wc,    const float* __restrict__ bc,
    float* __restrict__ out, int n)
{
    int d  = threadIdx.x;
    int r0 = blockIdx.x * 64;
    int r1 = min(r0 + 64, n);

    float sc = gamma[d] * rsqrtf(var[d] + 1e-5f);
    float sh = beta[d] - mean[d] * sc;
    float b1 = bias1[d];

    float local = 0.0f;
    for (int r = r0; r < r1; r++) {
        float o = g_acc[(size_t)r * 128 + d] / g_denom[r] + b1;
        local += o * sc + sh;
    }
    atomicAdd(&g_pool[d], local);
    __threadfence();

    __shared__ unsigned ticket;
    if (d == 0) ticket = atomicAdd(&g_ticket, 1u);
    __syncthreads();
    if (ticket != gridDim.x - 1) return;

    __shared__ float gsh[128];
    __shared__ float lg[5];
    gsh[d] = __ldcg(&g_pool[d]) / (float)n;
    __syncthreads();
    if (d < 5) {
        float s = bc[d];
#pragma unroll
        for (int k = 0; k < 128; k++) s += gsh[k] * Wc[k * 5 + d];
        lg[d] = s;
    }
    __syncthreads();
    if (d == 0) {
        float m = lg[0];
        for (int i = 1; i < 5; i++) m = fmaxf(m, lg[i]);
        float e[5], den = 0.f;
        for (int i = 0; i < 5; i++) { e[i] = expf(lg[i] - m); den += e[i]; }
        for (int i = 0; i < 5; i++) out[i] = e[i] / den;
    }
}

// ---------------- launcher ----------------
extern "C" void kernel_launch(void* const* d_in, const int* in_sizes, int n_in,
                              void* d_out, int out_size)
{
    const float* x     = (const float*)d_in[0];
    const int*   ei    = (const int*)d_in[1];
    const float* Wl    = (const float*)d_in[2];
    const float* bl    = (const float*)d_in[3];
    const float* Wr    = (const float*)d_in[4];
    const float* br    = (const float*)d_in[5];
    const float* att   = (const float*)d_in[6];
    const float* bias1 = (const float*)d_in[7];
    const float* gam   = (const float*)d_in[8];
    const float* bet   = (const float*)d_in[9];
    const float* mea   = (const float*)d_in[10];
    const float* var   = (const float*)d_in[11];
    const float* Wc    = (const float*)d_in[12];
    const float* bc    = (const float*)d_in[13];
    float* out = (float*)d_out;

    int n  = in_sizes[0] / 128;
    int E  = in_sizes[1] / 2;
    int TE = E + n;

    dim3 gg((n + 127) / 128, 2);
    gemm_kernel<<<gg, 256>>>(x, Wl, bl, Wr, br, n);

    int eb = (TE + 31) / 32;
    edge_fused_kernel<<<eb, 256>>>(ei, att, E, TE);

    node_kernel<<<(n + 63) / 64, 128>>>(bias1, gam, bet, mea, var, Wc, bc, out, n);
}

// round 7
// speedup vs baseline: 1.8345x; 1.0437x over previous
#include <cuda_runtime.h>
#include <cuda_bf16.h>
#include <math.h>

// ---------------- static scratch (no allocations allowed) ----------------
#define MAXN 50176

__device__ __align__(16) __nv_bfloat16 g_xl[MAXN * 128];
__device__ __align__(16) __nv_bfloat16 g_xr[MAXN * 128];
__device__ __align__(16) float g_acc[MAXN * 128];
__device__ float g_denom[MAXN];
__device__ float g_pool[128];
__device__ unsigned g_ticket;

__device__ __forceinline__ unsigned packbf2(float a, float b) {
    __nv_bfloat162 h = __float22bfloat162_rn(make_float2(a, b));
    return *(unsigned*)&h;
}

__device__ __forceinline__ void mma_bf16(float* c, const unsigned* a, unsigned b0, unsigned b1) {
    asm volatile(
        "mma.sync.aligned.m16n8k16.row.col.f32.bf16.bf16.f32 "
        "{%0,%1,%2,%3}, {%4,%5,%6,%7}, {%8,%9}, {%0,%1,%2,%3};\n"
        : "+f"(c[0]), "+f"(c[1]), "+f"(c[2]), "+f"(c[3])
        : "r"(a[0]), "r"(a[1]), "r"(a[2]), "r"(a[3]), "r"(b0), "r"(b1));
}

// ---------------- GEMM (bf16 tensor cores): out = bf16(x@W + b) ----------------
// grid = (ceil(n/128), 2): y=0 -> (Wl,bl)->g_xl, y=1 -> (Wr,br)->g_xr.
// 256 thr = 8 warps (4M x 2N), warp does 32x64 via 2x8 m16n8k16 tiles, K by 32.
// Smem holds bf16x2 "k-pairs": xs rows have pairs permuted so (q,q+4) adjacent
// (lds.64 A frags); ws2 rows are pair-indices with n permuted so nt-consecutive
// are adjacent (lds.128 B frags).
__global__ __launch_bounds__(256) void gemm_kernel(
    const float* __restrict__ x,
    const float* __restrict__ Wl, const float* __restrict__ bl,
    const float* __restrict__ Wr, const float* __restrict__ br,
    int n)
{
    __shared__ unsigned xs[128][20];   // 16 pairs used + pad
    __shared__ unsigned ws2[16][132];  // 16 k-pairs x 128 n + pad

    int row0 = blockIdx.x * 128;
    int t    = blockIdx.y;
    const float* W = t ? Wr : Wl;
    const float* b = t ? br : bl;
    __nv_bfloat16* outp = t ? g_xr : g_xl;

    int tid  = threadIdx.x;
    int lane = tid & 31;
    int wid  = tid >> 5;
    int wm   = wid & 3;
    int wn   = wid >> 2;

    // folded init
    if (t == 0) {
        float4 z = make_float4(0.f, 0.f, 0.f, 0.f);
        float4* accp = (float4*)(g_acc + (size_t)row0 * 128);
#pragma unroll
        for (int i = 0; i < 16; i++) accp[tid + i * 256] = z;
        if (tid < 128) g_denom[row0 + tid] = 0.0f;
        if (blockIdx.x == 0) {
            if (tid < 128) g_pool[tid] = 0.0f;
            if (tid == 0)  g_ticket = 0u;
        }
    }

    float c[16][4];
#pragma unroll
    for (int i = 0; i < 16; i++)
#pragma unroll
        for (int j = 0; j < 4; j++) c[i][j] = 0.0f;

    int q = lane & 3, r = lane >> 2;

    for (int k0 = 0; k0 < 128; k0 += 32) {
        // x tile: 128 rows x 32 k = 1024 float4 loads -> bf16x2 pairs
#pragma unroll
        for (int i = 0; i < 4; i++) {
            int idx = tid + i * 256;
            int rr = idx >> 3, c4 = idx & 7;
            float4 v = make_float4(0.f, 0.f, 0.f, 0.f);
            int gr = row0 + rr;
            if (gr < n) v = *(const float4*)(x + (size_t)gr * 128 + k0 + c4 * 4);
            unsigned* row = xs[rr];
            int g = c4 >> 2, m = c4 & 3;
            int p0 = 2 * m;            // pair indices p0, p0+1 within g-block
            int pos0 = ((p0 & 3) << 1) + (p0 >> 2);
            int p1 = p0 + 1;
            int pos1 = ((p1 & 3) << 1) + (p1 >> 2);
            row[g * 8 + pos0] = packbf2(v.x, v.y);
            row[g * 8 + pos1] = packbf2(v.z, v.w);
        }
        // W tile: 32 k x 128 n -> pairs (k,k+1) per n; 512 quad-stores
#pragma unroll
        for (int i = 0; i < 2; i++) {
            int idx = tid + i * 256;
            int kp = idx >> 5, c4 = idx & 31;
            int n0 = c4 * 4;
            float4 v0 = *(const float4*)(W + (size_t)(k0 + 2 * kp)     * 128 + n0);
            float4 v1 = *(const float4*)(W + (size_t)(k0 + 2 * kp + 1) * 128 + n0);
            unsigned* row = ws2[kp];
            const float* a0 = &v0.x;
            const float* a1 = &v1.x;
#pragma unroll
            for (int j = 0; j < 4; j++) {
                int nn = n0 + j;
                int pos = ((nn >> 6) << 6) + ((nn & 7) << 3) + ((nn & 63) >> 3);
                row[pos] = packbf2(a0[j], a1[j]);
            }
        }
        __syncthreads();

#pragma unroll
        for (int g = 0; g < 2; g++) {
            unsigned a[2][4];
#pragma unroll
            for (int mt = 0; mt < 2; mt++) {
                int rowA = wm * 32 + mt * 16 + r;
                uint2 lo = *(uint2*)&xs[rowA][g * 8 + 2 * q];       // pairs q, q+4
                uint2 hi = *(uint2*)&xs[rowA + 8][g * 8 + 2 * q];
                a[mt][0] = lo.x; a[mt][2] = lo.y;
                a[mt][1] = hi.x; a[mt][3] = hi.y;
            }
            int kb = g * 8 + q;
            uint4 b0a = *(uint4*)&ws2[kb][wn * 64 + r * 8];         // b0, nt 0..3
            uint4 b0b = *(uint4*)&ws2[kb][wn * 64 + r * 8 + 4];     // b0, nt 4..7
            uint4 b1a = *(uint4*)&ws2[kb + 4][wn * 64 + r * 8];     // b1, nt 0..3
            uint4 b1b = *(uint4*)&ws2[kb + 4][wn * 64 + r * 8 + 4];
            unsigned b0r[8] = {b0a.x, b0a.y, b0a.z, b0a.w, b0b.x, b0b.y, b0b.z, b0b.w};
            unsigned b1r[8] = {b1a.x, b1a.y, b1a.z, b1a.w, b1b.x, b1b.y, b1b.z, b1b.w};
#pragma unroll
            for (int mt = 0; mt < 2; mt++)
#pragma unroll
                for (int nt = 0; nt < 8; nt++)
                    mma_bf16(c[mt * 8 + nt], a[mt], b0r[nt], b1r[nt]);
        }
        __syncthreads();
    }

    // epilogue: +bias -> bf16x2 stores
#pragma unroll
    for (int mt = 0; mt < 2; mt++) {
#pragma unroll
        for (int nt = 0; nt < 8; nt++) {
            int col = wn * 64 + nt * 8 + 2 * q;
            float2 bb = *(const float2*)(b + col);
            int grow = row0 + wm * 32 + mt * 16 + r;
            float* cc = c[mt * 8 + nt];
            if (grow < n) {
                __nv_bfloat162 o = __float22bfloat162_rn(
                    make_float2(cc[0] + bb.x, cc[1] + bb.y));
                *(__nv_bfloat162*)(outp + (size_t)grow * 128 + col) = o;
            }
            if (grow + 8 < n) {
                __nv_bfloat162 o = __float22bfloat162_rn(
                    make_float2(cc[2] + bb.x, cc[3] + bb.y));
                *(__nv_bfloat162*)(outp + (size_t)(grow + 8) * 128 + col) = o;
            }
        }
    }
}

// ---------------- fused edge pass (bf16 gathers, fp32 RED) ----------------
__device__ __forceinline__ float lrelu(float v) { return v > 0.f ? v : 0.2f * v; }

__device__ __forceinline__ float4 ld_bf16x4(const __nv_bfloat16* p) {
    uint2 u = *(const uint2*)p;
    float2 f0 = __bfloat1622float2(*(__nv_bfloat162*)&u.x);
    float2 f1 = __bfloat1622float2(*(__nv_bfloat162*)&u.y);
    return make_float4(f0.x, f0.y, f1.x, f1.y);
}

__global__ __launch_bounds__(256) void edge_fused_kernel(
    const int* __restrict__ ei, const float* __restrict__ att, int E, int TE)
{
    int w    = (blockIdx.x * blockDim.x + threadIdx.x) >> 5;
    int lane = threadIdx.x & 31;
    int base = w * 4;
    if (base >= TE) return;

    float4 av = *(const float4*)(att + lane * 4);

    int s[4], d[4];
    bool ok[4];
#pragma unroll
    for (int k = 0; k < 4; k++) {
        int e = base + k;
        ok[k] = (e < TE);
        if (!ok[k]) { s[k] = 0; d[k] = 0; }
        else if (e < E) { s[k] = __ldg(ei + e); d[k] = __ldg(ei + E + e); }
        else { s[k] = d[k] = e - E; }
    }

    float4 xlv[4], xrv[4];
#pragma unroll
    for (int k = 0; k < 4; k++) {
        xlv[k] = ld_bf16x4(g_xl + (size_t)s[k] * 128 + lane * 4);
        xrv[k] = ld_bf16x4(g_xr + (size_t)d[k] * 128 + lane * 4);
    }

    float v[4];
#pragma unroll
    for (int k = 0; k < 4; k++) {
        v[k] = av.x * lrelu(xlv[k].x + xrv[k].x)
             + av.y * lrelu(xlv[k].y + xrv[k].y)
             + av.z * lrelu(xlv[k].z + xrv[k].z)
             + av.w * lrelu(xlv[k].w + xrv[k].w);
    }
#pragma unroll
    for (int o = 16; o; o >>= 1) {
#pragma unroll
        for (int k = 0; k < 4; k++)
            v[k] += __shfl_xor_sync(0xffffffffu, v[k], o);
    }

#pragma unroll
    for (int k = 0; k < 4; k++) {
        if (!ok[k]) continue;
        float wgt = __expf(v[k]);
        if (lane == 0) {
            asm volatile("red.global.add.f32 [%0], %1;"
                         :: "l"(g_denom + d[k]), "f"(wgt) : "memory");
        }
        float* dstp = g_acc + (size_t)d[k] * 128 + lane * 4;
        asm volatile("red.global.add.v4.f32 [%0], {%1, %2, %3, %4};"
                     :: "l"(dstp), "f"(wgt * xlv[k].x), "f"(wgt * xlv[k].y),
                        "f"(wgt * xlv[k].z), "f"(wgt * xlv[k].w)
                     : "memory");
    }
}

// ---------------- node pass + fused head ----------------
__global__ __launch_bounds__(128) void node_kernel(
    const float* __restrict__ bias1,
    const float* __restrict__ gamma, const float* __restrict__ beta,
    const float* __restrict__ mean,  const float* __restrict__ var,
    const float* __restrict__ Wc,    const float* __restrict__ bc,
    float* __restrict__ out, int n)
{
    int d  = threadIdx.x;
    int r0 = blockIdx.x * 64;
    int r1 = min(r0 + 64, n);

    float sc = gamma[d] * rsqrtf(var[d] + 1e-5f);
    float sh = beta[d] - mean[d] * sc;
    float b1 = bias1[d];

    float local = 0.0f;
    for (int r = r0; r < r1; r++) {
        float o = g_acc[(size_t)r * 128 + d] / g_denom[r] + b1;
        local += o * sc + sh;
    }
    atomicAdd(&g_pool[d], local);
    __threadfence();

    __shared__ unsigned ticket;
    if (d == 0) ticket = atomicAdd(&g_ticket, 1u);
    __syncthreads();
    if (ticket != gridDim.x - 1) return;

    __shared__ float gsh[128];
    __shared__ float lg[5];
    gsh[d] = __ldcg(&g_pool[d]) / (float)n;
    __syncthreads();
    if (d < 5) {
        float s = bc[d];
#pragma unroll
        for (int k = 0; k < 128; k++) s += gsh[k] * Wc[k * 5 + d];
        lg[d] = s;
    }
    __syncthreads();
    if (d == 0) {
        float m = lg[0];
        for (int i = 1; i < 5; i++) m = fmaxf(m, lg[i]);
        float e[5], den = 0.f;
        for (int i = 0; i < 5; i++) { e[i] = expf(lg[i] - m); den += e[i]; }
        for (int i = 0; i < 5; i++) out[i] = e[i] / den;
    }
}

// ---------------- launcher ----------------
extern "C" void kernel_launch(void* const* d_in, const int* in_sizes, int n_in,
                              void* d_out, int out_size)
{
    const float* x     = (const float*)d_in[0];
    const int*   ei    = (const int*)d_in[1];
    const float* Wl    = (const float*)d_in[2];
    const float* bl    = (const float*)d_in[3];
    const float* Wr    = (const float*)d_in[4];
    const float* br    = (const float*)d_in[5];
    const float* att   = (const float*)d_in[6];
    const float* bias1 = (const float*)d_in[7];
    const float* gam   = (const float*)d_in[8];
    const float* bet   = (const float*)d_in[9];
    const float* mea   = (const float*)d_in[10];
    const float* var   = (const float*)d_in[11];
    const float* Wc    = (const float*)d_in[12];
    const float* bc    = (const float*)d_in[13];
    float* out = (float*)d_out;

    int n  = in_sizes[0] / 128;
    int E  = in_sizes[1] / 2;
    int TE = E + n;

    dim3 gg((n + 127) / 128, 2);
    gemm_kernel<<<gg, 256>>>(x, Wl, bl, Wr, br, n);

    int eb = (TE + 31) / 32;
    edge_fused_kernel<<<eb, 256>>>(ei, att, E, TE);

    node_kernel<<<(n + 63) / 64, 128>>>(bias1, gam, bet, mea, var, Wc, bc, out, n);
}

// round 8
// speedup vs baseline: 2.0844x; 1.1362x over previous
#include <cuda_runtime.h>
#include <cuda_bf16.h>
#include <math.h>

// ---------------- static scratch (no allocations allowed) ----------------
#define MAXN 50176

__device__ __align__(16) __nv_bfloat16 g_xl[MAXN * 128];
__device__ __align__(16) __nv_bfloat16 g_xr[MAXN * 128];
__device__ __align__(16) __nv_bfloat16 g_acc[MAXN * 128];
__device__ float g_denom[MAXN];
__device__ float g_pool[128];
__device__ unsigned g_ticket;

__device__ __forceinline__ unsigned packbf2(float a, float b) {
    __nv_bfloat162 h = __float22bfloat162_rn(make_float2(a, b));
    return *(unsigned*)&h;
}

__device__ __forceinline__ void mma_bf16(float* c, const unsigned* a, unsigned b0, unsigned b1) {
    asm volatile(
        "mma.sync.aligned.m16n8k16.row.col.f32.bf16.bf16.f32 "
        "{%0,%1,%2,%3}, {%4,%5,%6,%7}, {%8,%9}, {%0,%1,%2,%3};\n"
        : "+f"(c[0]), "+f"(c[1]), "+f"(c[2]), "+f"(c[3])
        : "r"(a[0]), "r"(a[1]), "r"(a[2]), "r"(a[3]), "r"(b0), "r"(b1));
}

// store one float4 of x (row rr, float4-col c4 within 32-k chunk) as 2 bf16x2
// pairs into a staged x buffer row, permuted so A frags are lds.64.
__device__ __forceinline__ void store_xq(unsigned* xsbuf, int rr, int c4, float4 v) {
    unsigned* row = xsbuf + rr * 20;
    int g = c4 >> 2, m = c4 & 3;
    int p0 = 2 * m, p1 = p0 + 1;
    int pos0 = ((p0 & 3) << 1) + (p0 >> 2);
    int pos1 = ((p1 & 3) << 1) + (p1 >> 2);
    row[g * 8 + pos0] = packbf2(v.x, v.y);
    row[g * 8 + pos1] = packbf2(v.z, v.w);
}

// ---------------- GEMM (bf16 mma, pipelined): out = bf16(x@W + b) ----------------
// grid=(ceil(n/128),2). 256 thr = 8 warps (4Mx2N), warp 32x64 via 2x8 m16n8k16.
// Full W resident in smem (64 kp-rows x 132), x tiles double-buffered; one
// __syncthreads per 32-K chunk. 2 blocks/SM via launch_bounds reg cap.
#define XS_STRIDE 2560           // 128 rows * 20
#define WS_OFF    (2 * XS_STRIDE)
#define GEMM_SMEM ((WS_OFF + 64 * 132) * 4)

__global__ __launch_bounds__(256, 2) void gemm_kernel(
    const float* __restrict__ x,
    const float* __restrict__ Wl, const float* __restrict__ bl,
    const float* __restrict__ Wr, const float* __restrict__ br,
    int n)
{
    extern __shared__ unsigned dsm[];
    unsigned* wsf = dsm + WS_OFF;

    int row0 = blockIdx.x * 128;
    int t    = blockIdx.y;
    const float* W = t ? Wr : Wl;
    const float* b = t ? br : bl;
    __nv_bfloat16* outp = t ? g_xr : g_xl;

    int tid  = threadIdx.x;
    int lane = tid & 31;
    int wid  = tid >> 5;
    int wm   = wid & 3;
    int wn   = wid >> 2;

    // folded init: zero bf16 g_acc rows, denom, pool, ticket
    if (t == 0) {
        uint4 z = make_uint4(0u, 0u, 0u, 0u);
        uint4* accp = (uint4*)(g_acc + (size_t)row0 * 128);   // 32KB = 2048 uint4
#pragma unroll
        for (int i = 0; i < 8; i++) accp[tid + i * 256] = z;
        if (tid < 128) g_denom[row0 + tid] = 0.0f;
        if (blockIdx.x == 0) {
            if (tid < 128) g_pool[tid] = 0.0f;
            if (tid == 0)  g_ticket = 0u;
        }
    }

    // preload full W: 64 kp-rows x 128 n, permuted for lds.128 B frags
#pragma unroll
    for (int i = 0; i < 8; i++) {
        int idx = tid + i * 256;
        int kp = idx >> 5, c4 = idx & 31;
        int n0 = c4 * 4;
        float4 v0 = *(const float4*)(W + (size_t)(2 * kp)     * 128 + n0);
        float4 v1 = *(const float4*)(W + (size_t)(2 * kp + 1) * 128 + n0);
        const float* a0 = &v0.x;
        const float* a1 = &v1.x;
#pragma unroll
        for (int j = 0; j < 4; j++) {
            int nn = n0 + j;
            int pos = ((nn >> 6) << 6) + ((nn & 7) << 3) + ((nn & 63) >> 3);
            wsf[kp * 132 + pos] = packbf2(a0[j], a1[j]);
        }
    }

    // stage x chunk 0
#pragma unroll
    for (int i = 0; i < 4; i++) {
        int idx = tid + i * 256;
        int rr = idx >> 3, c4 = idx & 7;
        float4 v = make_float4(0.f, 0.f, 0.f, 0.f);
        int gr = row0 + rr;
        if (gr < n) v = *(const float4*)(x + (size_t)gr * 128 + c4 * 4);
        store_xq(dsm, rr, c4, v);
    }
    __syncthreads();

    float c[16][4];
#pragma unroll
    for (int i = 0; i < 16; i++)
#pragma unroll
        for (int j = 0; j < 4; j++) c[i][j] = 0.0f;

    int q = lane & 3, r = lane >> 2;
    int xrr = 0, xc4 = 0;

    for (int ch = 0; ch < 4; ch++) {
        unsigned* xcur = dsm + (ch & 1) * XS_STRIDE;
        unsigned* xnxt = dsm + ((ch + 1) & 1) * XS_STRIDE;

        // issue next-chunk global loads first (overlap with MMAs)
        float4 nv[4];
        if (ch < 3) {
            int k0 = (ch + 1) * 32;
#pragma unroll
            for (int i = 0; i < 4; i++) {
                int idx = tid + i * 256;
                int rr = idx >> 3, c4 = idx & 7;
                nv[i] = make_float4(0.f, 0.f, 0.f, 0.f);
                int gr = row0 + rr;
                if (gr < n) nv[i] = *(const float4*)(x + (size_t)gr * 128 + k0 + c4 * 4);
            }
            xrr = tid >> 3; xc4 = tid & 7;   // keep indices trivially recomputable
        }

#pragma unroll
        for (int g = 0; g < 2; g++) {
            unsigned a[2][4];
#pragma unroll
            for (int mt = 0; mt < 2; mt++) {
                int rowA = wm * 32 + mt * 16 + r;
                uint2 lo = *(uint2*)&xcur[rowA * 20 + g * 8 + 2 * q];
                uint2 hi = *(uint2*)&xcur[(rowA + 8) * 20 + g * 8 + 2 * q];
                a[mt][0] = lo.x; a[mt][2] = lo.y;
                a[mt][1] = hi.x; a[mt][3] = hi.y;
            }
            int kb = ch * 16 + g * 8 + q;
            uint4 b0a = *(uint4*)&wsf[kb * 132 + wn * 64 + r * 8];
            uint4 b0b = *(uint4*)&wsf[kb * 132 + wn * 64 + r * 8 + 4];
            uint4 b1a = *(uint4*)&wsf[(kb + 4) * 132 + wn * 64 + r * 8];
            uint4 b1b = *(uint4*)&wsf[(kb + 4) * 132 + wn * 64 + r * 8 + 4];
            unsigned b0r[8] = {b0a.x, b0a.y, b0a.z, b0a.w, b0b.x, b0b.y, b0b.z, b0b.w};
            unsigned b1r[8] = {b1a.x, b1a.y, b1a.z, b1a.w, b1b.x, b1b.y, b1b.z, b1b.w};
#pragma unroll
            for (int mt = 0; mt < 2; mt++)
#pragma unroll
                for (int nt = 0; nt < 8; nt++)
                    mma_bf16(c[mt * 8 + nt], a[mt], b0r[nt], b1r[nt]);
        }

        if (ch < 3) {
#pragma unroll
            for (int i = 0; i < 4; i++) {
                int idx = tid + i * 256;
                store_xq(xnxt, idx >> 3, idx & 7, nv[i]);
            }
        }
        __syncthreads();
    }

    // epilogue: +bias -> bf16x2 stores
#pragma unroll
    for (int mt = 0; mt < 2; mt++) {
#pragma unroll
        for (int nt = 0; nt < 8; nt++) {
            int col = wn * 64 + nt * 8 + 2 * q;
            float2 bb = *(const float2*)(b + col);
            int grow = row0 + wm * 32 + mt * 16 + r;
            float* cc = c[mt * 8 + nt];
            if (grow < n) {
                __nv_bfloat162 o = __float22bfloat162_rn(
                    make_float2(cc[0] + bb.x, cc[1] + bb.y));
                *(__nv_bfloat162*)(outp + (size_t)grow * 128 + col) = o;
            }
            if (grow + 8 < n) {
                __nv_bfloat162 o = __float22bfloat162_rn(
                    make_float2(cc[2] + bb.x, cc[3] + bb.y));
                *(__nv_bfloat162*)(outp + (size_t)(grow + 8) * 128 + col) = o;
            }
        }
    }
}

// ---------------- fused edge pass (bf16 gathers, bf16x2 RED) ----------------
__device__ __forceinline__ float lrelu(float v) { return v > 0.f ? v : 0.2f * v; }

__device__ __forceinline__ float4 ld_bf16x4(const __nv_bfloat16* p) {
    uint2 u = *(const uint2*)p;
    float2 f0 = __bfloat1622float2(*(__nv_bfloat162*)&u.x);
    float2 f1 = __bfloat1622float2(*(__nv_bfloat162*)&u.y);
    return make_float4(f0.x, f0.y, f1.x, f1.y);
}

__global__ __launch_bounds__(256) void edge_fused_kernel(
    const int* __restrict__ ei, const float* __restrict__ att, int E, int TE)
{
    int w    = (blockIdx.x * blockDim.x + threadIdx.x) >> 5;
    int lane = threadIdx.x & 31;
    int base = w * 4;
    if (base >= TE) return;

    float4 av = *(const float4*)(att + lane * 4);

    int s[4], d[4];
    bool ok[4];
#pragma unroll
    for (int k = 0; k < 4; k++) {
        int e = base + k;
        ok[k] = (e < TE);
        if (!ok[k]) { s[k] = 0; d[k] = 0; }
        else if (e < E) { s[k] = __ldg(ei + e); d[k] = __ldg(ei + E + e); }
        else { s[k] = d[k] = e - E; }
    }

    float4 xlv[4], xrv[4];
#pragma unroll
    for (int k = 0; k < 4; k++) {
        xlv[k] = ld_bf16x4(g_xl + (size_t)s[k] * 128 + lane * 4);
        xrv[k] = ld_bf16x4(g_xr + (size_t)d[k] * 128 + lane * 4);
    }

    float v[4];
#pragma unroll
    for (int k = 0; k < 4; k++) {
        v[k] = av.x * lrelu(xlv[k].x + xrv[k].x)
             + av.y * lrelu(xlv[k].y + xrv[k].y)
             + av.z * lrelu(xlv[k].z + xrv[k].z)
             + av.w * lrelu(xlv[k].w + xrv[k].w);
    }
#pragma unroll
    for (int o = 16; o; o >>= 1) {
#pragma unroll
        for (int k = 0; k < 4; k++)
            v[k] += __shfl_xor_sync(0xffffffffu, v[k], o);
    }

#pragma unroll
    for (int k = 0; k < 4; k++) {
        if (!ok[k]) continue;
        float wgt = __expf(v[k]);
        if (lane == 0) {
            asm volatile("red.global.add.f32 [%0], %1;"
                         :: "l"(g_denom + d[k]), "f"(wgt) : "memory");
        }
        unsigned p0 = packbf2(wgt * xlv[k].x, wgt * xlv[k].y);
        unsigned p1 = packbf2(wgt * xlv[k].z, wgt * xlv[k].w);
        __nv_bfloat16* dstp = g_acc + (size_t)d[k] * 128 + lane * 4;
        asm volatile("red.global.add.noftz.bf16x2 [%0], %1;"
                     :: "l"(dstp), "r"(p0) : "memory");
        asm volatile("red.global.add.noftz.bf16x2 [%0], %1;"
                     :: "l"(dstp + 2), "r"(p1) : "memory");
    }
}

// ---------------- node pass + fused head ----------------
__global__ __launch_bounds__(128) void node_kernel(
    const float* __restrict__ bias1,
    const float* __restrict__ gamma, const float* __restrict__ beta,
    const float* __restrict__ mean,  const float* __restrict__ var,
    const float* __restrict__ Wc,    const float* __restrict__ bc,
    float* __restrict__ out, int n)
{
    int d  = threadIdx.x;
    int r0 = blockIdx.x * 64;
    int r1 = min(r0 + 64, n);

    float sc = gamma[d] * rsqrtf(var[d] + 1e-5f);
    float sh = beta[d] - mean[d] * sc;
    float b1 = bias1[d];

    float local = 0.0f;
    for (int r = r0; r < r1; r++) {
        float a = __bfloat162float(g_acc[(size_t)r * 128 + d]);
        float o = a / g_denom[r] + b1;
        local += o * sc + sh;
    }
    atomicAdd(&g_pool[d], local);
    __threadfence();

    __shared__ unsigned ticket;
    if (d == 0) ticket = atomicAdd(&g_ticket, 1u);
    __syncthreads();
    if (ticket != gridDim.x - 1) return;

    __shared__ float gsh[128];
    __shared__ float lg[5];
    gsh[d] = __ldcg(&g_pool[d]) / (float)n;
    __syncthreads();
    if (d < 5) {
        float s = bc[d];
#pragma unroll
        for (int k = 0; k < 128; k++) s += gsh[k] * Wc[k * 5 + d];
        lg[d] = s;
    }
    __syncthreads();
    if (d == 0) {
        float m = lg[0];
        for (int i = 1; i < 5; i++) m = fmaxf(m, lg[i]);
        float e[5], den = 0.f;
        for (int i = 0; i < 5; i++) { e[i] = expf(lg[i] - m); den += e[i]; }
        for (int i = 0; i < 5; i++) out[i] = e[i] / den;
    }
}

// ---------------- launcher ----------------
extern "C" void kernel_launch(void* const* d_in, const int* in_sizes, int n_in,
                              void* d_out, int out_size)
{
    const float* x     = (const float*)d_in[0];
    const int*   ei    = (const int*)d_in[1];
    const float* Wl    = (const float*)d_in[2];
    const float* bl    = (const float*)d_in[3];
    const float* Wr    = (const float*)d_in[4];
    const float* br    = (const float*)d_in[5];
    const float* att   = (const float*)d_in[6];
    const float* bias1 = (const float*)d_in[7];
    const float* gam   = (const float*)d_in[8];
    const float* bet   = (const float*)d_in[9];
    const float* mea   = (const float*)d_in[10];
    const float* var   = (const float*)d_in[11];
    const float* Wc    = (const float*)d_in[12];
    const float* bc    = (const float*)d_in[13];
    float* out = (float*)d_out;

    int n  = in_sizes[0] / 128;
    int E  = in_sizes[1] / 2;
    int TE = E + n;

    static int smem_set = 0;
    if (!smem_set) {
        cudaFuncSetAttribute(gemm_kernel,
                             cudaFuncAttributeMaxDynamicSharedMemorySize, GEMM_SMEM);
        smem_set = 1;
    }

    dim3 gg((n + 127) / 128, 2);
    gemm_kernel<<<gg, 256, GEMM_SMEM>>>(x, Wl, bl, Wr, br, n);

    int eb = (TE + 31) / 32;
    edge_fused_kernel<<<eb, 256>>>(ei, att, E, TE);

    node_kernel<<<(n + 63) / 64, 128>>>(bias1, gam, bet, mea, var, Wc, bc, out, n);
}